// round 6
// baseline (speedup 1.0000x reference)
#include <cuda_runtime.h>
#include <math.h>

#define BB 64
#define QQ 4096
#define NN 256
#define NL 21
#define INF_REPLACE 1000000.0f

#define GD   8                       // bins per axis
#define NCELL (GD*GD*GD)             // 512
#define INV_CELL (GD / 50.0f)        // 0.16
#define CAP  16                      // targets per cell (overflow -> full scan)
#define QCH  1024                    // q rows per fixup block

// ---------------- Kernel 1: stream INF_REPLACE over the whole output --------
__global__ __launch_bounds__(256) void fill_kernel(float4* __restrict__ out)
{
    const float4 v = make_float4(INF_REPLACE, INF_REPLACE, INF_REPLACE, INF_REPLACE);
    const int n4 = BB * QQ * NN / 4;              // 16,777,216
    const int stride = gridDim.x * blockDim.x;
    for (int i = blockIdx.x * blockDim.x + threadIdx.x; i < n4; i += stride)
        out[i] = v;
}

// ---------------- exact cost for a near pair (reference arithmetic) ---------
__device__ __noinline__ float exact_cost(
    const float* __restrict__ logits, const int* __restrict__ labels,
    const float* __restrict__ tboxes, const float* __restrict__ pboxes,
    int b, int q, int n,
    float pcx, float pcy, float pcz, float dist)
{
    const float* pb = pboxes + ((size_t)b * QQ + q) * 6;
    const float psx = __ldg(pb + 3), psy = __ldg(pb + 4), psz = __ldg(pb + 5);

    const float* tb = tboxes + ((size_t)b * NN + n) * 6;
    const float tcx = __ldg(tb + 0), tcy = __ldg(tb + 1), tcz = __ldg(tb + 2);
    const float tsx = __ldg(tb + 3), tsy = __ldg(tb + 4), tsz = __ldg(tb + 5);

    float ix = fminf(pcx + 0.5f*psx, tcx + 0.5f*tsx) - fmaxf(pcx - 0.5f*psx, tcx - 0.5f*tsx);
    float iy = fminf(pcy + 0.5f*psy, tcy + 0.5f*tsy) - fmaxf(pcy - 0.5f*psy, tcy - 0.5f*tsy);
    float iz = fminf(pcz + 0.5f*psz, tcz + 0.5f*tsz) - fmaxf(pcz - 0.5f*psz, tcz - 0.5f*tsz);
    ix = fmaxf(ix, 0.0f); iy = fmaxf(iy, 0.0f); iz = fmaxf(iz, 0.0f);

    const float inter = ix * iy * iz;
    const float vol1 = psx * psy * psz;
    const float vol2 = tsx * tsy * tsz;
    const float uni  = vol1 + vol2 - inter;
    const float iou  = (uni > 0.0f) ? (inter / uni) : 0.0f;

    const float* lg = logits + ((size_t)b * QQ + q) * NL;
    const int lbl = __ldg(labels + b * NN + n);
    float s = 0.0f, el = 0.0f;
    #pragma unroll
    for (int c = 0; c < NL; c++) {
        const float e = expf(__ldg(lg + c));
        s += e;
        if (c == lbl) el = e;
    }
    const float cls = -(el / s);
    return cls + 5.0f * dist + 2.0f * (1.0f - iou);
}

// ---------------- Kernel 2: spatial-hash fixup of near pairs ----------------
__global__ __launch_bounds__(256) void fixup_kernel(
    const float* __restrict__ logits,    // [B, Q, 21]
    const float* __restrict__ pboxes,    // [B, Q, 6]
    const int*   __restrict__ labels,    // [B, N]
    const float* __restrict__ tboxes,    // [B, N, 6]
    float*       __restrict__ out)       // [B, Q, N]
{
    const int b  = blockIdx.y;
    const int q0 = blockIdx.x * QCH;
    const int t  = threadIdx.x;

    __shared__ float4        s_tc[NN];          // target centers
    __shared__ int           s_cnt[NCELL];
    __shared__ unsigned char s_bin[NCELL * CAP];
    __shared__ int           s_ovf;

    for (int i = t; i < NCELL; i += 256) s_cnt[i] = 0;
    if (t == 0) s_ovf = 0;
    __syncthreads();

    // bin target t
    {
        const float* tb = tboxes + ((size_t)b * NN + t) * 6;
        const float x = __ldg(tb + 0), y = __ldg(tb + 1), z = __ldg(tb + 2);
        s_tc[t] = make_float4(x, y, z, 0.0f);
        const int cx = min(GD - 1, max(0, (int)(x * INV_CELL)));
        const int cy = min(GD - 1, max(0, (int)(y * INV_CELL)));
        const int cz = min(GD - 1, max(0, (int)(z * INV_CELL)));
        const int c  = (cz * GD + cy) * GD + cx;
        const int old = atomicAdd(&s_cnt[c], 1);
        if (old < CAP) s_bin[c * CAP + old] = (unsigned char)t;
        else           atomicExch(&s_ovf, 1);
    }
    __syncthreads();
    const bool ovf = (s_ovf != 0);

    for (int row = t; row < QCH; row += 256) {
        const int q = q0 + row;
        const float* pb = pboxes + ((size_t)b * QQ + q) * 6;
        const float px = __ldg(pb + 0), py = __ldg(pb + 1), pz = __ldg(pb + 2);

        if (ovf) {
            // correctness fallback (astronomically rare): scan all targets
            for (int n = 0; n < NN; n++) {
                const float4 tc = s_tc[n];
                const float dx = px - tc.x, dy = py - tc.y, dz = pz - tc.z;
                const float dist = sqrtf(dx*dx + dy*dy + dz*dz);
                if (dist <= 2.0f)
                    out[((size_t)b * QQ + q) * NN + n] =
                        exact_cost(logits, labels, tboxes, pboxes, b, q, n, px, py, pz, dist);
            }
        } else {
            const int xlo = max(0, (int)((px - 2.0f) * INV_CELL));
            const int xhi = min(GD - 1, (int)((px + 2.0f) * INV_CELL));
            const int ylo = max(0, (int)((py - 2.0f) * INV_CELL));
            const int yhi = min(GD - 1, (int)((py + 2.0f) * INV_CELL));
            const int zlo = max(0, (int)((pz - 2.0f) * INV_CELL));
            const int zhi = min(GD - 1, (int)((pz + 2.0f) * INV_CELL));

            for (int cz = zlo; cz <= zhi; cz++)
            for (int cy = ylo; cy <= yhi; cy++)
            for (int cx = xlo; cx <= xhi; cx++) {
                const int c   = (cz * GD + cy) * GD + cx;
                const int cnt = s_cnt[c];
                for (int k = 0; k < cnt; k++) {
                    const int n = s_bin[c * CAP + k];
                    const float4 tc = s_tc[n];
                    const float dx = px - tc.x, dy = py - tc.y, dz = pz - tc.z;
                    const float dist = sqrtf(dx*dx + dy*dy + dz*dz);
                    if (dist <= 2.0f)
                        out[((size_t)b * QQ + q) * NN + n] =
                            exact_cost(logits, labels, tboxes, pboxes, b, q, n, px, py, pz, dist);
                }
            }
        }
    }
}

extern "C" void kernel_launch(void* const* d_in, const int* in_sizes, int n_in,
                              void* d_out, int out_size)
{
    const float* logits = (const float*)d_in[0];  // [B,Q,21]
    const float* pboxes = (const float*)d_in[1];  // [B,Q,6]
    const int*   labels = (const int*)  d_in[2];  // [B,N]
    const float* tboxes = (const float*)d_in[3];  // [B,N,6]
    float*       out    = (float*)d_out;          // [B,Q,N]

    fill_kernel<<<2048, 256>>>((float4*)out);

    dim3 fgrid(QQ / QCH, BB);                     // (4, 64) = 256 blocks
    fixup_kernel<<<fgrid, 256>>>(logits, pboxes, labels, tboxes, out);
}

// round 7
// speedup vs baseline: 1.3165x; 1.3165x over previous
#include <cuda_runtime.h>
#include <math.h>

#define BB 64
#define QQ 4096
#define NN 256
#define NL 21
#define INF_REPLACE 1000000.0f

#define GD   8                       // bins per axis
#define NCELL (GD*GD*GD)             // 512
#define INV_CELL (GD / 50.0f)        // 0.16
#define CAP  16                      // targets per cell (overflow -> full scan)
#define QROWS 256                    // q rows per fixup block (1 per thread)

// ---------------- Kernel 1: stream INF_REPLACE over the whole output --------
__global__ __launch_bounds__(256) void fill_kernel(float4* __restrict__ out)
{
    const float4 v = make_float4(INF_REPLACE, INF_REPLACE, INF_REPLACE, INF_REPLACE);
    const int n4 = BB * QQ * NN / 4;              // 16,777,216
    const int stride = gridDim.x * blockDim.x;
    #pragma unroll 4
    for (int i = blockIdx.x * blockDim.x + threadIdx.x; i < n4; i += stride)
        out[i] = v;
}

// ---------------- exact cost for a near pair (reference arithmetic) ---------
__device__ __noinline__ float exact_cost(
    const float* __restrict__ logits, const int* __restrict__ labels,
    const float* __restrict__ tboxes, const float* __restrict__ pboxes,
    int b, int q, int n,
    float pcx, float pcy, float pcz, float dist)
{
    const float* pb = pboxes + ((size_t)b * QQ + q) * 6;
    const float psx = __ldg(pb + 3), psy = __ldg(pb + 4), psz = __ldg(pb + 5);

    const float* tb = tboxes + ((size_t)b * NN + n) * 6;
    const float tcx = __ldg(tb + 0), tcy = __ldg(tb + 1), tcz = __ldg(tb + 2);
    const float tsx = __ldg(tb + 3), tsy = __ldg(tb + 4), tsz = __ldg(tb + 5);

    float ix = fminf(pcx + 0.5f*psx, tcx + 0.5f*tsx) - fmaxf(pcx - 0.5f*psx, tcx - 0.5f*tsx);
    float iy = fminf(pcy + 0.5f*psy, tcy + 0.5f*tsy) - fmaxf(pcy - 0.5f*psy, tcy - 0.5f*tsy);
    float iz = fminf(pcz + 0.5f*psz, tcz + 0.5f*tsz) - fmaxf(pcz - 0.5f*psz, tcz - 0.5f*tsz);
    ix = fmaxf(ix, 0.0f); iy = fmaxf(iy, 0.0f); iz = fmaxf(iz, 0.0f);

    const float inter = ix * iy * iz;
    const float vol1 = psx * psy * psz;
    const float vol2 = tsx * tsy * tsz;
    const float uni  = vol1 + vol2 - inter;
    const float iou  = (uni > 0.0f) ? (inter / uni) : 0.0f;

    const float* lg = logits + ((size_t)b * QQ + q) * NL;
    const int lbl = __ldg(labels + b * NN + n);
    float s = 0.0f, el = 0.0f;
    #pragma unroll
    for (int c = 0; c < NL; c++) {
        const float e = expf(__ldg(lg + c));
        s += e;
        if (c == lbl) el = e;
    }
    const float cls = -(el / s);
    return cls + 5.0f * dist + 2.0f * (1.0f - iou);
}

// ---------------- Kernel 2: spatial-hash fixup, one q-row per thread --------
__global__ __launch_bounds__(256) void fixup_kernel(
    const float* __restrict__ logits,    // [B, Q, 21]
    const float* __restrict__ pboxes,    // [B, Q, 6]
    const int*   __restrict__ labels,    // [B, N]
    const float* __restrict__ tboxes,    // [B, N, 6]
    float*       __restrict__ out)       // [B, Q, N]
{
    const int b  = blockIdx.y;
    const int q  = blockIdx.x * QROWS + threadIdx.x;   // this thread's row
    const int t  = threadIdx.x;

    __shared__ float4        s_tc[NN];          // target centers
    __shared__ int           s_cnt[NCELL];
    __shared__ unsigned char s_bin[NCELL * CAP];
    __shared__ int           s_ovf;

    // prefetch this row's pred center (overlaps hash build latency)
    const float* pb = pboxes + ((size_t)b * QQ + q) * 6;
    const float px = __ldg(pb + 0);
    const float py = __ldg(pb + 1);
    const float pz = __ldg(pb + 2);

    for (int i = t; i < NCELL; i += 256) s_cnt[i] = 0;
    if (t == 0) s_ovf = 0;
    __syncthreads();

    // bin target t
    {
        const float* tb = tboxes + ((size_t)b * NN + t) * 6;
        const float x = __ldg(tb + 0), y = __ldg(tb + 1), z = __ldg(tb + 2);
        s_tc[t] = make_float4(x, y, z, 0.0f);
        const int cx = min(GD - 1, max(0, (int)(x * INV_CELL)));
        const int cy = min(GD - 1, max(0, (int)(y * INV_CELL)));
        const int cz = min(GD - 1, max(0, (int)(z * INV_CELL)));
        const int c  = (cz * GD + cy) * GD + cx;
        const int old = atomicAdd(&s_cnt[c], 1);
        if (old < CAP) s_bin[c * CAP + old] = (unsigned char)t;
        else           atomicExch(&s_ovf, 1);
    }
    __syncthreads();

    if (s_ovf != 0) {
        // correctness fallback (astronomically rare): scan all targets
        for (int n = 0; n < NN; n++) {
            const float4 tc = s_tc[n];
            const float dx = px - tc.x, dy = py - tc.y, dz = pz - tc.z;
            const float dist = sqrtf(dx*dx + dy*dy + dz*dz);
            if (dist <= 2.0f)
                out[((size_t)b * QQ + q) * NN + n] =
                    exact_cost(logits, labels, tboxes, pboxes, b, q, n, px, py, pz, dist);
        }
        return;
    }

    const int xlo = max(0, (int)((px - 2.0f) * INV_CELL));
    const int xhi = min(GD - 1, (int)((px + 2.0f) * INV_CELL));
    const int ylo = max(0, (int)((py - 2.0f) * INV_CELL));
    const int yhi = min(GD - 1, (int)((py + 2.0f) * INV_CELL));
    const int zlo = max(0, (int)((pz - 2.0f) * INV_CELL));
    const int zhi = min(GD - 1, (int)((pz + 2.0f) * INV_CELL));

    for (int cz = zlo; cz <= zhi; cz++)
    for (int cy = ylo; cy <= yhi; cy++)
    for (int cx = xlo; cx <= xhi; cx++) {
        const int c   = (cz * GD + cy) * GD + cx;
        const int cnt = s_cnt[c];
        for (int k = 0; k < cnt; k++) {
            const int n = s_bin[c * CAP + k];
            const float4 tc = s_tc[n];
            const float dx = px - tc.x, dy = py - tc.y, dz = pz - tc.z;
            const float dist = sqrtf(dx*dx + dy*dy + dz*dz);
            if (dist <= 2.0f)
                out[((size_t)b * QQ + q) * NN + n] =
                    exact_cost(logits, labels, tboxes, pboxes, b, q, n, px, py, pz, dist);
        }
    }
}

extern "C" void kernel_launch(void* const* d_in, const int* in_sizes, int n_in,
                              void* d_out, int out_size)
{
    const float* logits = (const float*)d_in[0];  // [B,Q,21]
    const float* pboxes = (const float*)d_in[1];  // [B,Q,6]
    const int*   labels = (const int*)  d_in[2];  // [B,N]
    const float* tboxes = (const float*)d_in[3];  // [B,N,6]
    float*       out    = (float*)d_out;          // [B,Q,N]

    fill_kernel<<<148 * 16, 256>>>((float4*)out);

    dim3 fgrid(QQ / QROWS, BB);                   // (16, 64) = 1024 blocks
    fixup_kernel<<<fgrid, 256>>>(logits, pboxes, labels, tboxes, out);
}